// round 1
// baseline (speedup 1.0000x reference)
#include <cuda_runtime.h>

// Problem constants
#define N_OP   50000
#define N_DEV  5000
#define D      128
#define DE     16
#define FIN    144        // D + DE
#define OUTF   128
#define OUT_STRIDE 256    // D + OUTF

// ---------------------------------------------------------------------------
// Scratch: per-etype accumulators (sum of concat[src_feat, ef]) + edge counts
// Layout (floats):
//   acc_prev  [50000*144] @ 0
//   acc_succ  [50000*144] @ 7,200,000
//   acc_serve [50000*144] @ 14,400,000
//   acc_link  [ 5000*144] @ 21,600,000
//   acc_place [ 5000*144] @ 22,320,000
//   cnt_prev  [50000]     @ 23,040,000
//   cnt_succ  [50000]     @ 23,090,000
//   cnt_serve [50000]     @ 23,140,000
//   cnt_link  [ 5000]     @ 23,190,000
//   cnt_place [ 5000]     @ 23,195,000
// total = 23,200,000 floats (92.8 MB)
// ---------------------------------------------------------------------------
#define OFF_ACC_PREV   0
#define OFF_ACC_SUCC   7200000
#define OFF_ACC_SERVE  14400000
#define OFF_ACC_LINK   21600000
#define OFF_ACC_PLACE  22320000
#define OFF_CNT_PREV   23040000
#define OFF_CNT_SUCC   23090000
#define OFF_CNT_SERVE  23140000
#define OFF_CNT_LINK   23190000
#define OFF_CNT_PLACE  23195000
#define SCRATCH_FLOATS 23200000

__device__ float g_scratch[SCRATCH_FLOATS];

// ---------------------------------------------------------------------------
// Zero scratch (float4, one-shot)
// ---------------------------------------------------------------------------
__global__ void zero_kernel(float* __restrict__ p, int n4) {
    int i = blockIdx.x * blockDim.x + threadIdx.x;
    if (i < n4) {
        float4 z = make_float4(0.f, 0.f, 0.f, 0.f);
        reinterpret_cast<float4*>(p)[i] = z;
    }
}

// ---------------------------------------------------------------------------
// Vector atomic reduce (sm_90+): red.global.add.v4.f32
// ---------------------------------------------------------------------------
__device__ __forceinline__ void red_add_v4(float* addr, float4 v) {
    asm volatile("red.global.add.v4.f32 [%0], {%1, %2, %3, %4};"
                 :: "l"(addr), "f"(v.x), "f"(v.y), "f"(v.z), "f"(v.w)
                 : "memory");
}

// ---------------------------------------------------------------------------
// Scatter: one warp per edge.
//   lanes 0..31: gather float4 of src feats  -> red into acc[dst][lane*4..]
//   lanes 0..3 : float4 of edge feats        -> red into acc[dst][128 + lane*4..]
//   lane 0     : count += 1
// ---------------------------------------------------------------------------
__global__ void scatter_kernel(const float* __restrict__ src_feats,
                               const float* __restrict__ ef,
                               const int*   __restrict__ src,
                               const int*   __restrict__ dst,
                               float* __restrict__ acc,
                               float* __restrict__ cnt,
                               int ne) {
    int w    = (blockIdx.x * blockDim.x + threadIdx.x) >> 5;
    int lane = threadIdx.x & 31;
    if (w >= ne) return;

    int s = src[w];
    int d = dst[w];

    const float4* srow = reinterpret_cast<const float4*>(src_feats + (size_t)s * D);
    float* arow = acc + (size_t)d * FIN;

    float4 v = srow[lane];                 // 32 lanes cover 128 floats
    red_add_v4(arow + lane * 4, v);

    if (lane < 4) {
        float4 e4 = reinterpret_cast<const float4*>(ef + (size_t)w * DE)[lane];
        red_add_v4(arow + D + lane * 4, e4);
    }
    if (lane == 0) {
        atomicAdd(cnt + d, 1.0f);
    }
}

// ---------------------------------------------------------------------------
// Fused GEMM + mean-gate + average + ReLU + feats-copy.
//   For each dst node row: for each etype,
//     p = acc_row[144] @ W[144,128]
//     if cnt>0: out += p/cnt + b
//   out = relu(out / NET); also copy input feats to cols [0,128).
//
// Tiling: block = 128 rows x 128 cols, 512 threads.
//   thread: r = tid&31 (rows r, r+32, r+64, r+96), cg = tid>>5 (cols cg*8..+7)
//   K chunked 4 x 36. smem: Ws 36x128 (18.4KB) + As 128x37 padded (18.9KB)
// ---------------------------------------------------------------------------
template<int NET>
__global__ __launch_bounds__(512)
void gemm_combine_kernel(const float* __restrict__ feats,
                         const float* __restrict__ acc0, const float* __restrict__ cnt0,
                         const float* __restrict__ W0,   const float* __restrict__ b0,
                         const float* __restrict__ acc1, const float* __restrict__ cnt1,
                         const float* __restrict__ W1,   const float* __restrict__ b1,
                         const float* __restrict__ acc2, const float* __restrict__ cnt2,
                         const float* __restrict__ W2,   const float* __restrict__ b2,
                         float* __restrict__ out, int n) {
    __shared__ float Ws[36 * 128];
    __shared__ float As[128 * 37];

    const int tid  = threadIdx.x;
    const int r    = tid & 31;
    const int cg   = tid >> 5;          // 0..15
    const int c0   = cg * 8;
    const int row0 = blockIdx.x * 128;

    const float* accs[3] = {acc0, acc1, acc2};
    const float* cnts[3] = {cnt0, cnt1, cnt2};
    const float* Wts[3]  = {W0, W1, W2};
    const float* bs[3]   = {b0, b1, b2};

    float outv[4][8];
    #pragma unroll
    for (int q = 0; q < 4; q++)
        #pragma unroll
        for (int j = 0; j < 8; j++) outv[q][j] = 0.f;

    for (int et = 0; et < NET; et++) {
        const float* acc = accs[et];
        const float* W   = Wts[et];

        float p[4][8];
        #pragma unroll
        for (int q = 0; q < 4; q++)
            #pragma unroll
            for (int j = 0; j < 8; j++) p[q][j] = 0.f;

        for (int kc = 0; kc < 4; kc++) {
            __syncthreads();
            // load W chunk: rows [kc*36, kc*36+36) x 128 cols = 4608 floats
            #pragma unroll
            for (int i = 0; i < 9; i++) {
                int idx = tid + i * 512;
                Ws[idx] = W[kc * 36 * 128 + idx];
            }
            // load A chunk: 128 rows x 36 k = 4608 floats (padded stride 37)
            #pragma unroll
            for (int i = 0; i < 9; i++) {
                int idx = tid + i * 512;
                int rr  = idx / 36;
                int cc  = idx - rr * 36;
                int row = row0 + rr;
                As[rr * 37 + cc] =
                    (row < n) ? acc[(size_t)row * FIN + kc * 36 + cc] : 0.f;
            }
            __syncthreads();

            #pragma unroll
            for (int k = 0; k < 36; k++) {
                float a0 = As[(r      ) * 37 + k];
                float a1 = As[(r + 32 ) * 37 + k];
                float a2 = As[(r + 64 ) * 37 + k];
                float a3 = As[(r + 96 ) * 37 + k];
                #pragma unroll
                for (int j = 0; j < 8; j++) {
                    float w = Ws[k * 128 + c0 + j];   // broadcast within warp
                    p[0][j] += a0 * w;
                    p[1][j] += a1 * w;
                    p[2][j] += a2 * w;
                    p[3][j] += a3 * w;
                }
            }
        }

        // per-etype epilogue: mean gating + bias
        const float* cnt = cnts[et];
        const float* b   = bs[et];
        #pragma unroll
        for (int q = 0; q < 4; q++) {
            int row = row0 + r + q * 32;
            if (row < n) {
                float c = cnt[row];
                if (c > 0.f) {
                    float inv = 1.0f / c;
                    #pragma unroll
                    for (int j = 0; j < 8; j++)
                        outv[q][j] += p[q][j] * inv + b[c0 + j];
                }
            }
        }
    }

    const float invn = 1.0f / (float)NET;
    #pragma unroll
    for (int q = 0; q < 4; q++) {
        int row = row0 + r + q * 32;
        if (row < n) {
            float*       orow = out   + (size_t)row * OUT_STRIDE;
            const float* frow = feats + (size_t)row * D;
            #pragma unroll
            for (int j = 0; j < 8; j++) {
                orow[c0 + j]     = frow[c0 + j];                      // identity copy
                orow[D + c0 + j] = fmaxf(outv[q][j] * invn, 0.f);     // relu(mean)
            }
        }
    }
}

// ---------------------------------------------------------------------------
// Launch
// Inputs (metadata order):
//  0 op_feats [50000,128]  1 device_feats [5000,128]
//  link : 2 ef, 3 src, 4 dst, 5 W, 6 b   (device -> device, ne=80000)
//  prev : 7..11                          (op -> op,        ne=600000)
//  succ : 12..16                         (op -> op)
//  place: 17..21                         (op -> device)
//  serve: 22..26                         (device -> op)
// Output: op_out [50000,256] at 0, device_out [5000,256] at 12,800,000
// ---------------------------------------------------------------------------
extern "C" void kernel_launch(void* const* d_in, const int* in_sizes, int n_in,
                              void* d_out, int out_size) {
    const float* op_feats  = (const float*)d_in[0];
    const float* dev_feats = (const float*)d_in[1];

    const float* ef_link  = (const float*)d_in[2];
    const int*   src_link = (const int*)  d_in[3];
    const int*   dst_link = (const int*)  d_in[4];
    const float* W_link   = (const float*)d_in[5];
    const float* b_link   = (const float*)d_in[6];

    const float* ef_prev  = (const float*)d_in[7];
    const int*   src_prev = (const int*)  d_in[8];
    const int*   dst_prev = (const int*)  d_in[9];
    const float* W_prev   = (const float*)d_in[10];
    const float* b_prev   = (const float*)d_in[11];

    const float* ef_succ  = (const float*)d_in[12];
    const int*   src_succ = (const int*)  d_in[13];
    const int*   dst_succ = (const int*)  d_in[14];
    const float* W_succ   = (const float*)d_in[15];
    const float* b_succ   = (const float*)d_in[16];

    const float* ef_place  = (const float*)d_in[17];
    const int*   src_place = (const int*)  d_in[18];
    const int*   dst_place = (const int*)  d_in[19];
    const float* W_place   = (const float*)d_in[20];
    const float* b_place   = (const float*)d_in[21];

    const float* ef_serve  = (const float*)d_in[22];
    const int*   src_serve = (const int*)  d_in[23];
    const int*   dst_serve = (const int*)  d_in[24];
    const float* W_serve   = (const float*)d_in[25];
    const float* b_serve   = (const float*)d_in[26];

    const int ne_link  = in_sizes[3];
    const int ne_prev  = in_sizes[8];
    const int ne_succ  = in_sizes[13];
    const int ne_place = in_sizes[18];
    const int ne_serve = in_sizes[23];

    float* scratch = nullptr;
    cudaGetSymbolAddress((void**)&scratch, g_scratch);

    float* acc_prev  = scratch + OFF_ACC_PREV;
    float* acc_succ  = scratch + OFF_ACC_SUCC;
    float* acc_serve = scratch + OFF_ACC_SERVE;
    float* acc_link  = scratch + OFF_ACC_LINK;
    float* acc_place = scratch + OFF_ACC_PLACE;
    float* cnt_prev  = scratch + OFF_CNT_PREV;
    float* cnt_succ  = scratch + OFF_CNT_SUCC;
    float* cnt_serve = scratch + OFF_CNT_SERVE;
    float* cnt_link  = scratch + OFF_CNT_LINK;
    float* cnt_place = scratch + OFF_CNT_PLACE;

    float* out = (float*)d_out;
    float* out_op  = out;
    float* out_dev = out + (size_t)N_OP * OUT_STRIDE;

    // 1) zero accumulators + counts
    {
        int n4 = SCRATCH_FLOATS / 4;
        zero_kernel<<<(n4 + 255) / 256, 256>>>(scratch, n4);
    }

    // 2) scatter-add per edge type (one warp per edge)
    auto scat_grid = [](int ne) { return (ne * 32 + 255) / 256; };
    scatter_kernel<<<scat_grid(ne_prev),  256>>>(op_feats,  ef_prev,  src_prev,  dst_prev,  acc_prev,  cnt_prev,  ne_prev);
    scatter_kernel<<<scat_grid(ne_succ),  256>>>(op_feats,  ef_succ,  src_succ,  dst_succ,  acc_succ,  cnt_succ,  ne_succ);
    scatter_kernel<<<scat_grid(ne_serve), 256>>>(dev_feats, ef_serve, src_serve, dst_serve, acc_serve, cnt_serve, ne_serve);
    scatter_kernel<<<scat_grid(ne_link),  256>>>(dev_feats, ef_link,  src_link,  dst_link,  acc_link,  cnt_link,  ne_link);
    scatter_kernel<<<scat_grid(ne_place), 256>>>(op_feats,  ef_place, src_place, dst_place, acc_place, cnt_place, ne_place);

    // 3) fused GEMM + gate + average + relu + feats copy
    {
        int grid_op  = (N_OP  + 127) / 128;
        int grid_dev = (N_DEV + 127) / 128;
        gemm_combine_kernel<3><<<grid_op, 512>>>(
            op_feats,
            acc_prev,  cnt_prev,  W_prev,  b_prev,
            acc_succ,  cnt_succ,  W_succ,  b_succ,
            acc_serve, cnt_serve, W_serve, b_serve,
            out_op, N_OP);
        gemm_combine_kernel<2><<<grid_dev, 512>>>(
            dev_feats,
            acc_link,  cnt_link,  W_link,  b_link,
            acc_place, cnt_place, W_place, b_place,
            nullptr,   nullptr,   nullptr, nullptr,
            out_dev, N_DEV);
    }

    (void)n_in; (void)out_size;
}

// round 3
// speedup vs baseline: 1.1293x; 1.1293x over previous
#include <cuda_runtime.h>

// Problem constants
#define N_OP   50000
#define N_DEV  5000
#define D      128
#define DE     16
#define FIN    144        // D + DE
#define OUTF   128
#define OUT_STRIDE 256    // D + OUTF

#define NE_TOTAL 2480000  // 80000 + 4*600000
#define NSEG     160000   // 3*50000 + 2*5000

// Segment bases in the concatenated per-(etype,dst) counter space
#define SEG_PREV   0
#define SEG_SUCC   50000
#define SEG_SERVE  100000
#define SEG_LINK   150000
#define SEG_PLACE  155000

// ---------------------------------------------------------------------------
// Scratch
// ---------------------------------------------------------------------------
#define OFF_ACC_PREV   0
#define OFF_ACC_SUCC   7200000
#define OFF_ACC_SERVE  14400000
#define OFF_ACC_LINK   21600000
#define OFF_ACC_PLACE  22320000
#define ACC_FLOATS     23040000

__device__ float g_acc[ACC_FLOATS];
__device__ int   g_cnt[NSEG];
__device__ int   g_off[NSEG];
__device__ int   g_cur[NSEG];
__device__ int   g_tilesum[256];
__device__ int   g_slots[NE_TOTAL];

// ---------------------------------------------------------------------------
// Zero the counters
// ---------------------------------------------------------------------------
__global__ void zero_cnt_kernel(int* __restrict__ p, int n) {
    int i = blockIdx.x * blockDim.x + threadIdx.x;
    if (i < n) p[i] = 0;
}

// ---------------------------------------------------------------------------
// Histogram: one thread per edge across all 5 etypes (stacked ranges)
// ---------------------------------------------------------------------------
__global__ void hist_kernel(const int* __restrict__ d0, int n0,
                            const int* __restrict__ d1, int n1,
                            const int* __restrict__ d2, int n2,
                            const int* __restrict__ d3, int n3,
                            const int* __restrict__ d4, int n4) {
    int i = blockIdx.x * blockDim.x + threadIdx.x;
    if (i < n0) { atomicAdd(&g_cnt[SEG_PREV  + d0[i]], 1); return; } i -= n0;
    if (i < n1) { atomicAdd(&g_cnt[SEG_SUCC  + d1[i]], 1); return; } i -= n1;
    if (i < n2) { atomicAdd(&g_cnt[SEG_SERVE + d2[i]], 1); return; } i -= n2;
    if (i < n3) { atomicAdd(&g_cnt[SEG_LINK  + d3[i]], 1); return; } i -= n3;
    if (i < n4) { atomicAdd(&g_cnt[SEG_PLACE + d4[i]], 1); }
}

// ---------------------------------------------------------------------------
// Exclusive scan over g_cnt (NSEG elements): 3 kernels
// ---------------------------------------------------------------------------
__global__ __launch_bounds__(1024)
void scan_tiles_kernel(const int* __restrict__ cnt, int* __restrict__ off,
                       int* __restrict__ tilesum, int n) {
    __shared__ int warp_sums[32];
    int tid  = threadIdx.x;
    int gid  = blockIdx.x * 1024 + tid;
    int lane = tid & 31, wid = tid >> 5;
    int v = (gid < n) ? cnt[gid] : 0;

    int x = v;
    #pragma unroll
    for (int d = 1; d < 32; d <<= 1) {
        int y = __shfl_up_sync(0xffffffffu, x, d);
        if (lane >= d) x += y;
    }
    if (lane == 31) warp_sums[wid] = x;
    __syncthreads();
    if (wid == 0) {
        int s = warp_sums[lane];
        #pragma unroll
        for (int d = 1; d < 32; d <<= 1) {
            int y = __shfl_up_sync(0xffffffffu, s, d);
            if (lane >= d) s += y;
        }
        warp_sums[lane] = s;
    }
    __syncthreads();
    int warp_off = (wid > 0) ? warp_sums[wid - 1] : 0;
    int incl = x + warp_off;
    if (gid < n) off[gid] = incl - v;            // exclusive within tile
    if (tid == 1023) tilesum[blockIdx.x] = incl; // tile total
}

__global__ void scan_sums_kernel(int* __restrict__ tilesum, int ntiles) {
    __shared__ int s[256];
    int tid = threadIdx.x;
    if (tid < ntiles) s[tid] = tilesum[tid];
    __syncthreads();
    if (tid == 0) {
        int acc = 0;
        for (int i = 0; i < ntiles; i++) { int t = s[i]; s[i] = acc; acc += t; }
    }
    __syncthreads();
    if (tid < ntiles) tilesum[tid] = s[tid];
}

__global__ void add_offsets_kernel(int* __restrict__ off,
                                   const int* __restrict__ tilesum,
                                   int* __restrict__ cur, int n) {
    int i = blockIdx.x * blockDim.x + threadIdx.x;
    if (i < n) {
        int o = off[i] + tilesum[i >> 10];
        off[i] = o;
        cur[i] = o;
    }
}

// ---------------------------------------------------------------------------
// Binning: scatter local edge index into dst buckets (global slot pool)
// ---------------------------------------------------------------------------
__global__ void bin_kernel(const int* __restrict__ d0, int n0,
                           const int* __restrict__ d1, int n1,
                           const int* __restrict__ d2, int n2,
                           const int* __restrict__ d3, int n3,
                           const int* __restrict__ d4, int n4) {
    int i = blockIdx.x * blockDim.x + threadIdx.x;
    int e = i;
    if (e < n0) { int s = atomicAdd(&g_cur[SEG_PREV  + d0[e]], 1); g_slots[s] = e; return; } e -= n0;
    if (e < n1) { int s = atomicAdd(&g_cur[SEG_SUCC  + d1[e]], 1); g_slots[s] = e; return; } e -= n1;
    if (e < n2) { int s = atomicAdd(&g_cur[SEG_SERVE + d2[e]], 1); g_slots[s] = e; return; } e -= n2;
    if (e < n3) { int s = atomicAdd(&g_cur[SEG_LINK  + d3[e]], 1); g_slots[s] = e; return; } e -= n3;
    if (e < n4) { int s = atomicAdd(&g_cur[SEG_PLACE + d4[e]], 1); g_slots[s] = e; }
}

// ---------------------------------------------------------------------------
// Gather: one warp per dst node. Lanes batch-load 32 edge+src IDs; per edge,
// one broadcast float4 gather per lane (128 floats warp-wide) + 4 FADD; lanes
// 0..3 accumulate the 16 edge features. Each acc row is written exactly once
// with no atomics. Rows with cnt==0 are never written (GEMM gates on cnt>0).
// ---------------------------------------------------------------------------
__global__ __launch_bounds__(256)
void gather_kernel(const float* __restrict__ src_feats,
                   const float* __restrict__ ef,
                   const int*   __restrict__ src,
                   float* __restrict__ acc,
                   int seg_base, int n_dst) {
    int g = blockIdx.x * (blockDim.x >> 5) + (threadIdx.x >> 5);
    if (g >= n_dst) return;
    int lane = threadIdx.x & 31;

    int m = g_cnt[seg_base + g];
    if (m == 0) return;
    int base = g_off[seg_base + g];

    float4 f  = make_float4(0.f, 0.f, 0.f, 0.f);
    float4 e4 = make_float4(0.f, 0.f, 0.f, 0.f);

    for (int c = 0; c < m; c += 32) {
        int k = c + lane;
        int eidx = 0, sidx = 0;
        if (k < m) {
            eidx = __ldg(&g_slots[base + k]);
            sidx = __ldg(&src[eidx]);
        }
        int iter = min(32, m - c);
        #pragma unroll 4
        for (int i = 0; i < iter; i++) {
            int e = __shfl_sync(0xffffffffu, eidx, i);
            int s = __shfl_sync(0xffffffffu, sidx, i);
            float4 v = __ldg(reinterpret_cast<const float4*>(src_feats + (size_t)s * D) + lane);
            f.x += v.x; f.y += v.y; f.z += v.z; f.w += v.w;
            if (lane < 4) {
                float4 t = __ldg(reinterpret_cast<const float4*>(ef + (size_t)e * DE) + lane);
                e4.x += t.x; e4.y += t.y; e4.z += t.z; e4.w += t.w;
            }
        }
    }

    float* arow = acc + (size_t)g * FIN;
    reinterpret_cast<float4*>(arow)[lane] = f;
    if (lane < 4) reinterpret_cast<float4*>(arow + D)[lane] = e4;
}

// ---------------------------------------------------------------------------
// Fused GEMM + mean-gate + average + ReLU + feats-copy.
// block = 128 rows x 128 cols, 512 threads, K chunked 4 x 36.
// ---------------------------------------------------------------------------
template<int NET>
__global__ __launch_bounds__(512)
void gemm_combine_kernel(const float* __restrict__ feats,
                         const float* __restrict__ acc0, const int* __restrict__ cnt0,
                         const float* __restrict__ W0,   const float* __restrict__ b0,
                         const float* __restrict__ acc1, const int* __restrict__ cnt1,
                         const float* __restrict__ W1,   const float* __restrict__ b1,
                         const float* __restrict__ acc2, const int* __restrict__ cnt2,
                         const float* __restrict__ W2,   const float* __restrict__ b2,
                         float* __restrict__ out, int n) {
    __shared__ float Ws[36 * 128];
    __shared__ float As[128 * 37];

    const int tid  = threadIdx.x;
    const int r    = tid & 31;
    const int cg   = tid >> 5;          // 0..15
    const int c0   = cg * 8;
    const int row0 = blockIdx.x * 128;

    const float* accs[3] = {acc0, acc1, acc2};
    const int*   cnts[3] = {cnt0, cnt1, cnt2};
    const float* Wts[3]  = {W0, W1, W2};
    const float* bs[3]   = {b0, b1, b2};

    float outv[4][8];
    #pragma unroll
    for (int q = 0; q < 4; q++)
        #pragma unroll
        for (int j = 0; j < 8; j++) outv[q][j] = 0.f;

    for (int et = 0; et < NET; et++) {
        const float* acc = accs[et];
        const float* W   = Wts[et];

        float p[4][8];
        #pragma unroll
        for (int q = 0; q < 4; q++)
            #pragma unroll
            for (int j = 0; j < 8; j++) p[q][j] = 0.f;

        for (int kc = 0; kc < 4; kc++) {
            __syncthreads();
            #pragma unroll
            for (int i = 0; i < 9; i++) {
                int idx = tid + i * 512;
                Ws[idx] = W[kc * 36 * 128 + idx];
            }
            #pragma unroll
            for (int i = 0; i < 9; i++) {
                int idx = tid + i * 512;
                int rr  = idx / 36;
                int cc  = idx - rr * 36;
                int row = row0 + rr;
                As[rr * 37 + cc] =
                    (row < n) ? acc[(size_t)row * FIN + kc * 36 + cc] : 0.f;
            }
            __syncthreads();

            #pragma unroll
            for (int k = 0; k < 36; k++) {
                float a0 = As[(r      ) * 37 + k];
                float a1 = As[(r + 32 ) * 37 + k];
                float a2 = As[(r + 64 ) * 37 + k];
                float a3 = As[(r + 96 ) * 37 + k];
                #pragma unroll
                for (int j = 0; j < 8; j++) {
                    float w = Ws[k * 128 + c0 + j];
                    p[0][j] += a0 * w;
                    p[1][j] += a1 * w;
                    p[2][j] += a2 * w;
                    p[3][j] += a3 * w;
                }
            }
        }

        const int*   cnt = cnts[et];
        const float* b   = bs[et];
        #pragma unroll
        for (int q = 0; q < 4; q++) {
            int row = row0 + r + q * 32;
            if (row < n) {
                int c = cnt[row];
                if (c > 0) {
                    float inv = 1.0f / (float)c;
                    #pragma unroll
                    for (int j = 0; j < 8; j++)
                        outv[q][j] += p[q][j] * inv + b[c0 + j];
                }
            }
        }
    }

    const float invn = 1.0f / (float)NET;
    #pragma unroll
    for (int q = 0; q < 4; q++) {
        int row = row0 + r + q * 32;
        if (row < n) {
            float*       orow = out   + (size_t)row * OUT_STRIDE;
            const float* frow = feats + (size_t)row * D;
            #pragma unroll
            for (int j = 0; j < 8; j++) {
                orow[c0 + j]     = frow[c0 + j];
                orow[D + c0 + j] = fmaxf(outv[q][j] * invn, 0.f);
            }
        }
    }
}

// ---------------------------------------------------------------------------
// Launch
// ---------------------------------------------------------------------------
extern "C" void kernel_launch(void* const* d_in, const int* in_sizes, int n_in,
                              void* d_out, int out_size) {
    const float* op_feats  = (const float*)d_in[0];
    const float* dev_feats = (const float*)d_in[1];

    const float* ef_link  = (const float*)d_in[2];
    const int*   src_link = (const int*)  d_in[3];
    const int*   dst_link = (const int*)  d_in[4];
    const float* W_link   = (const float*)d_in[5];
    const float* b_link   = (const float*)d_in[6];

    const float* ef_prev  = (const float*)d_in[7];
    const int*   src_prev = (const int*)  d_in[8];
    const int*   dst_prev = (const int*)  d_in[9];
    const float* W_prev   = (const float*)d_in[10];
    const float* b_prev   = (const float*)d_in[11];

    const float* ef_succ  = (const float*)d_in[12];
    const int*   src_succ = (const int*)  d_in[13];
    const int*   dst_succ = (const int*)  d_in[14];
    const float* W_succ   = (const float*)d_in[15];
    const float* b_succ   = (const float*)d_in[16];

    const float* ef_place  = (const float*)d_in[17];
    const int*   src_place = (const int*)  d_in[18];
    const int*   dst_place = (const int*)  d_in[19];
    const float* W_place   = (const float*)d_in[20];
    const float* b_place   = (const float*)d_in[21];

    const float* ef_serve  = (const float*)d_in[22];
    const int*   src_serve = (const int*)  d_in[23];
    const int*   dst_serve = (const int*)  d_in[24];
    const float* W_serve   = (const float*)d_in[25];
    const float* b_serve   = (const float*)d_in[26];

    const int ne_link  = in_sizes[3];
    const int ne_prev  = in_sizes[8];
    const int ne_succ  = in_sizes[13];
    const int ne_place = in_sizes[18];
    const int ne_serve = in_sizes[23];
    const int ne_total = ne_link + ne_prev + ne_succ + ne_place + ne_serve;

    float* accbase = nullptr;
    cudaGetSymbolAddress((void**)&accbase, g_acc);
    int* cntbase = nullptr;
    cudaGetSymbolAddress((void**)&cntbase, g_cnt);
    int* offbase = nullptr;
    cudaGetSymbolAddress((void**)&offbase, g_off);
    int* curbase = nullptr;
    cudaGetSymbolAddress((void**)&curbase, g_cur);
    int* tilesum = nullptr;
    cudaGetSymbolAddress((void**)&tilesum, g_tilesum);

    float* acc_prev  = accbase + OFF_ACC_PREV;
    float* acc_succ  = accbase + OFF_ACC_SUCC;
    float* acc_serve = accbase + OFF_ACC_SERVE;
    float* acc_link  = accbase + OFF_ACC_LINK;
    float* acc_place = accbase + OFF_ACC_PLACE;

    float* out = (float*)d_out;
    float* out_op  = out;
    float* out_dev = out + (size_t)N_OP * OUT_STRIDE;

    // 1) zero counters
    zero_cnt_kernel<<<(NSEG + 255) / 256, 256>>>(cntbase, NSEG);

    // 2) histogram (stacked edge order: prev, succ, serve, link, place)
    hist_kernel<<<(ne_total + 255) / 256, 256>>>(
        dst_prev, ne_prev, dst_succ, ne_succ, dst_serve, ne_serve,
        dst_link, ne_link, dst_place, ne_place);

    // 3) exclusive scan over counters
    {
        int ntiles = (NSEG + 1023) / 1024;  // 157
        scan_tiles_kernel<<<ntiles, 1024>>>(cntbase, offbase, tilesum, NSEG);
        scan_sums_kernel<<<1, 256>>>(tilesum, ntiles);
        add_offsets_kernel<<<(NSEG + 255) / 256, 256>>>(offbase, tilesum, curbase, NSEG);
    }

    // 4) bin edge IDs into dst buckets
    bin_kernel<<<(ne_total + 255) / 256, 256>>>(
        dst_prev, ne_prev, dst_succ, ne_succ, dst_serve, ne_serve,
        dst_link, ne_link, dst_place, ne_place);

    // 5) gather per etype (one warp per dst node)
    {
        const int WPB = 256 / 32;
        gather_kernel<<<(N_OP  + WPB - 1) / WPB, 256>>>(op_feats,  ef_prev,  src_prev,  acc_prev,  SEG_PREV,  N_OP);
        gather_kernel<<<(N_OP  + WPB - 1) / WPB, 256>>>(op_feats,  ef_succ,  src_succ,  acc_succ,  SEG_SUCC,  N_OP);
        gather_kernel<<<(N_OP  + WPB - 1) / WPB, 256>>>(dev_feats, ef_serve, src_serve, acc_serve, SEG_SERVE, N_OP);
        gather_kernel<<<(N_DEV + WPB - 1) / WPB, 256>>>(dev_feats, ef_link,  src_link,  acc_link,  SEG_LINK,  N_DEV);
        gather_kernel<<<(N_DEV + WPB - 1) / WPB, 256>>>(op_feats,  ef_place, src_place, acc_place, SEG_PLACE, N_DEV);
    }

    // 6) fused GEMM + gate + average + relu + feats copy
    {
        int grid_op  = (N_OP  + 127) / 128;
        int grid_dev = (N_DEV + 127) / 128;
        gemm_combine_kernel<3><<<grid_op, 512>>>(
            op_feats,
            acc_prev,  cntbase + SEG_PREV,  W_prev,  b_prev,
            acc_succ,  cntbase + SEG_SUCC,  W_succ,  b_succ,
            acc_serve, cntbase + SEG_SERVE, W_serve, b_serve,
            out_op, N_OP);
        gemm_combine_kernel<2><<<grid_dev, 512>>>(
            dev_feats,
            acc_link,  cntbase + SEG_LINK,  W_link,  b_link,
            acc_place, cntbase + SEG_PLACE, W_place, b_place,
            nullptr,   nullptr,             nullptr, nullptr,
            out_dev, N_DEV);
    }

    (void)n_in; (void)out_size;
}

// round 5
// speedup vs baseline: 1.8309x; 1.6213x over previous
#include <cuda_runtime.h>

// Problem constants
#define N_OP   50000
#define N_DEV  5000
#define D      128
#define DE     16
#define FIN    144        // D + DE
#define OUTF   128
#define OUT_STRIDE 256    // D + OUTF

#define NE_TOTAL 2480000
#define NSEG     160000

// Segment bases (stacked order: prev, succ, serve, link, place)
#define SEG_PREV   0
#define SEG_SUCC   50000
#define SEG_SERVE  100000
#define SEG_LINK   150000
#define SEG_PLACE  155000

#define OFF_ACC_PREV   0
#define OFF_ACC_SUCC   7200000
#define OFF_ACC_SERVE  14400000
#define OFF_ACC_LINK   21600000
#define OFF_ACC_PLACE  22320000
#define ACC_FLOATS     23040000

#define GRID_OP  391      // ceil(50000/128)
#define GRID_DEV 40       // ceil(5000/128)

__device__ float g_acc[ACC_FLOATS];
__device__ int   g_cnt[NSEG];
__device__ int   g_off[NSEG];
__device__ int   g_cur[NSEG];
__device__ int   g_tilesum[256];
__device__ int   g_slots[NE_TOTAL];

// ---------------------------------------------------------------------------
// f32x2 packed math helpers (sm_100a)
// ---------------------------------------------------------------------------
__device__ __forceinline__ void ffma2(unsigned long long& acc,
                                      unsigned long long a,
                                      unsigned long long b) {
    asm("fma.rn.f32x2 %0, %1, %2, %0;" : "+l"(acc) : "l"(a), "l"(b));
}
__device__ __forceinline__ unsigned long long pack_dup(float x) {
    unsigned long long r;
    asm("mov.b64 %0, {%1, %1};" : "=l"(r) : "f"(x));
    return r;
}
__device__ __forceinline__ float2 unpack2(unsigned long long v) {
    float2 f;
    asm("mov.b64 {%0, %1}, %2;" : "=f"(f.x), "=f"(f.y) : "l"(v));
    return f;
}

// ---------------------------------------------------------------------------
// 0) zero counters
// ---------------------------------------------------------------------------
__global__ void zero_cnt_kernel(int* __restrict__ p, int n) {
    int i = blockIdx.x * blockDim.x + threadIdx.x;
    if (i < n) p[i] = 0;
}

// ---------------------------------------------------------------------------
// 1) histogram over all edges (stacked)
// ---------------------------------------------------------------------------
__global__ void hist_kernel(const int* __restrict__ d0, int n0,
                            const int* __restrict__ d1, int n1,
                            const int* __restrict__ d2, int n2,
                            const int* __restrict__ d3, int n3,
                            const int* __restrict__ d4, int n4) {
    int i = blockIdx.x * blockDim.x + threadIdx.x;
    if (i < n0) { atomicAdd(&g_cnt[SEG_PREV  + d0[i]], 1); return; } i -= n0;
    if (i < n1) { atomicAdd(&g_cnt[SEG_SUCC  + d1[i]], 1); return; } i -= n1;
    if (i < n2) { atomicAdd(&g_cnt[SEG_SERVE + d2[i]], 1); return; } i -= n2;
    if (i < n3) { atomicAdd(&g_cnt[SEG_LINK  + d3[i]], 1); return; } i -= n3;
    if (i < n4) { atomicAdd(&g_cnt[SEG_PLACE + d4[i]], 1); }
}

// ---------------------------------------------------------------------------
// 2) per-tile exclusive scan (1024/tile) + tile totals
// ---------------------------------------------------------------------------
__global__ __launch_bounds__(1024)
void scan_tiles_kernel(const int* __restrict__ cnt, int* __restrict__ off,
                       int* __restrict__ tilesum, int n) {
    __shared__ int warp_sums[32];
    int tid  = threadIdx.x;
    int gid  = blockIdx.x * 1024 + tid;
    int lane = tid & 31, wid = tid >> 5;
    int v = (gid < n) ? cnt[gid] : 0;

    int x = v;
    #pragma unroll
    for (int d = 1; d < 32; d <<= 1) {
        int y = __shfl_up_sync(0xffffffffu, x, d);
        if (lane >= d) x += y;
    }
    if (lane == 31) warp_sums[wid] = x;
    __syncthreads();
    if (wid == 0) {
        int s = warp_sums[lane];
        #pragma unroll
        for (int d = 1; d < 32; d <<= 1) {
            int y = __shfl_up_sync(0xffffffffu, s, d);
            if (lane >= d) s += y;
        }
        warp_sums[lane] = s;
    }
    __syncthreads();
    int warp_off = (wid > 0) ? warp_sums[wid - 1] : 0;
    int incl = x + warp_off;
    if (gid < n) off[gid] = incl - v;
    if (tid == 1023) tilesum[blockIdx.x] = incl;
}

// ---------------------------------------------------------------------------
// 3) fixup: add prefix of tile sums, init cursors (one block per tile)
// ---------------------------------------------------------------------------
__global__ __launch_bounds__(1024)
void scan_fixup_kernel(int* __restrict__ off, const int* __restrict__ tilesum,
                       int* __restrict__ cur, int n) {
    __shared__ int red[32];
    __shared__ int s_prefix;
    int t    = blockIdx.x;
    int tid  = threadIdx.x;
    int lane = tid & 31, wid = tid >> 5;

    int partial = 0;
    for (int i = tid; i < t; i += 1024) partial += tilesum[i];
    #pragma unroll
    for (int d = 16; d > 0; d >>= 1)
        partial += __shfl_down_sync(0xffffffffu, partial, d);
    if (lane == 0) red[wid] = partial;
    __syncthreads();
    if (tid < 32) {
        int v = red[tid];
        #pragma unroll
        for (int d = 16; d > 0; d >>= 1)
            v += __shfl_down_sync(0xffffffffu, v, d);
        if (tid == 0) s_prefix = v;
    }
    __syncthreads();
    int prefix = s_prefix;

    int gid = t * 1024 + tid;
    if (gid < n) {
        int o = off[gid] + prefix;
        off[gid] = o;
        cur[gid] = o;
    }
}

// ---------------------------------------------------------------------------
// 4) bin edge IDs into dst buckets
// ---------------------------------------------------------------------------
__global__ void bin_kernel(const int* __restrict__ d0, int n0,
                           const int* __restrict__ d1, int n1,
                           const int* __restrict__ d2, int n2,
                           const int* __restrict__ d3, int n3,
                           const int* __restrict__ d4, int n4) {
    int e = blockIdx.x * blockDim.x + threadIdx.x;
    if (e < n0) { int s = atomicAdd(&g_cur[SEG_PREV  + d0[e]], 1); g_slots[s] = e; return; } e -= n0;
    if (e < n1) { int s = atomicAdd(&g_cur[SEG_SUCC  + d1[e]], 1); g_slots[s] = e; return; } e -= n1;
    if (e < n2) { int s = atomicAdd(&g_cur[SEG_SERVE + d2[e]], 1); g_slots[s] = e; return; } e -= n2;
    if (e < n3) { int s = atomicAdd(&g_cur[SEG_LINK  + d3[e]], 1); g_slots[s] = e; return; } e -= n3;
    if (e < n4) { int s = atomicAdd(&g_cur[SEG_PLACE + d4[e]], 1); g_slots[s] = e; }
}

// ---------------------------------------------------------------------------
// 5) fused gather: one warp per (etype, dst) segment across all 5 etypes
// ---------------------------------------------------------------------------
__global__ __launch_bounds__(256)
void gather_fused_kernel(const float* __restrict__ op_feats,
                         const float* __restrict__ dev_feats,
                         const float* __restrict__ ef_prev,  const int* __restrict__ src_prev,
                         const float* __restrict__ ef_succ,  const int* __restrict__ src_succ,
                         const float* __restrict__ ef_serve, const int* __restrict__ src_serve,
                         const float* __restrict__ ef_link,  const int* __restrict__ src_link,
                         const float* __restrict__ ef_place, const int* __restrict__ src_place) {
    int seg = blockIdx.x * 8 + (threadIdx.x >> 5);
    if (seg >= NSEG) return;
    int lane = threadIdx.x & 31;

    const float* sf; const float* ef; const int* src; float* acc; int local;
    if (seg < SEG_SUCC)       { sf = op_feats;  ef = ef_prev;  src = src_prev;  acc = g_acc + OFF_ACC_PREV;  local = seg; }
    else if (seg < SEG_SERVE) { sf = op_feats;  ef = ef_succ;  src = src_succ;  acc = g_acc + OFF_ACC_SUCC;  local = seg - SEG_SUCC; }
    else if (seg < SEG_LINK)  { sf = dev_feats; ef = ef_serve; src = src_serve; acc = g_acc + OFF_ACC_SERVE; local = seg - SEG_SERVE; }
    else if (seg < SEG_PLACE) { sf = dev_feats; ef = ef_link;  src = src_link;  acc = g_acc + OFF_ACC_LINK;  local = seg - SEG_LINK; }
    else                      { sf = op_feats;  ef = ef_place; src = src_place; acc = g_acc + OFF_ACC_PLACE; local = seg - SEG_PLACE; }

    int m = g_cnt[seg];
    if (m == 0) return;
    int base = g_off[seg];

    float4 f  = make_float4(0.f, 0.f, 0.f, 0.f);
    float4 e4 = make_float4(0.f, 0.f, 0.f, 0.f);

    for (int c = 0; c < m; c += 32) {
        int k = c + lane;
        int eidx = 0, sidx = 0;
        if (k < m) {
            eidx = __ldg(&g_slots[base + k]);
            sidx = __ldg(&src[eidx]);
        }
        int iter = min(32, m - c);
        #pragma unroll 4
        for (int i = 0; i < iter; i++) {
            int e = __shfl_sync(0xffffffffu, eidx, i);
            int s = __shfl_sync(0xffffffffu, sidx, i);
            float4 v = __ldg(reinterpret_cast<const float4*>(sf + (size_t)s * D) + lane);
            f.x += v.x; f.y += v.y; f.z += v.z; f.w += v.w;
            if (lane < 4) {
                float4 t = __ldg(reinterpret_cast<const float4*>(ef + (size_t)e * DE) + lane);
                e4.x += t.x; e4.y += t.y; e4.z += t.z; e4.w += t.w;
            }
        }
    }

    float* arow = acc + (size_t)local * FIN;
    reinterpret_cast<float4*>(arow)[lane] = f;
    if (lane < 4) reinterpret_cast<float4*>(arow + D)[lane] = e4;
}

// ---------------------------------------------------------------------------
// 6) fused GEMM (op + dev tiles in one grid), whole-K smem residency, f32x2.
//    smem: As[128*145] + Ws[144*128]  (147,968 B dynamic)
// ---------------------------------------------------------------------------
#define AS_STRIDE 145
#define AS_FLOATS (128 * AS_STRIDE)   // 18560
#define WS_FLOATS (144 * 128)         // 18432
#define GEMM_SMEM_BYTES ((AS_FLOATS + WS_FLOATS) * 4)

__global__ __launch_bounds__(512)
void gemm_fused_kernel(const float* __restrict__ op_feats,
                       const float* __restrict__ dev_feats,
                       const float* __restrict__ W_prev,  const float* __restrict__ b_prev,
                       const float* __restrict__ W_succ,  const float* __restrict__ b_succ,
                       const float* __restrict__ W_serve, const float* __restrict__ b_serve,
                       const float* __restrict__ W_link,  const float* __restrict__ b_link,
                       const float* __restrict__ W_place, const float* __restrict__ b_place,
                       float* __restrict__ out) {
    extern __shared__ float sm[];
    float* As = sm;                 // [128][145]
    float* Ws = sm + AS_FLOATS;     // [144][128]

    const int tid = threadIdx.x;
    const int r   = tid & 31;
    const int c0  = (tid >> 5) * 8;

    const bool is_op = blockIdx.x < GRID_OP;
    const int  net   = is_op ? 3 : 2;
    const int  row0  = (is_op ? blockIdx.x : (blockIdx.x - GRID_OP)) * 128;
    const int  n     = is_op ? N_OP : N_DEV;

    const float* feats = is_op ? op_feats : dev_feats;
    const float* accA[3]; const int* cntA[3]; const float* WA[3]; const float* bA[3];
    if (is_op) {
        accA[0] = g_acc + OFF_ACC_PREV;  cntA[0] = g_cnt + SEG_PREV;  WA[0] = W_prev;  bA[0] = b_prev;
        accA[1] = g_acc + OFF_ACC_SUCC;  cntA[1] = g_cnt + SEG_SUCC;  WA[1] = W_succ;  bA[1] = b_succ;
        accA[2] = g_acc + OFF_ACC_SERVE; cntA[2] = g_cnt + SEG_SERVE; WA[2] = W_serve; bA[2] = b_serve;
    } else {
        accA[0] = g_acc + OFF_ACC_LINK;  cntA[0] = g_cnt + SEG_LINK;  WA[0] = W_link;  bA[0] = b_link;
        accA[1] = g_acc + OFF_ACC_PLACE; cntA[1] = g_cnt + SEG_PLACE; WA[1] = W_place; bA[1] = b_place;
        accA[2] = accA[1]; cntA[2] = cntA[1]; WA[2] = WA[1]; bA[2] = bA[1];
    }
    float* outp = is_op ? out : (out + (size_t)N_OP * OUT_STRIDE);

    float outv[4][8];
    #pragma unroll
    for (int q = 0; q < 4; q++)
        #pragma unroll
        for (int j = 0; j < 8; j++) outv[q][j] = 0.f;

    for (int et = 0; et < net; et++) {
        const float* acc = accA[et];
        const float* W   = WA[et];

        __syncthreads();
        // load W: 18432 floats = 4608 float4, 9 per thread
        {
            const float4* W4 = reinterpret_cast<const float4*>(W);
            float4* Ws4 = reinterpret_cast<float4*>(Ws);
            #pragma unroll
            for (int i = 0; i < 9; i++) Ws4[tid + i * 512] = W4[tid + i * 512];
        }
        // load A tile: 128 rows x 144 = 4608 float4, 9 per thread, pad-store
        {
            #pragma unroll
            for (int i = 0; i < 9; i++) {
                int idx = tid + i * 512;
                int rr  = idx / 36;
                int cc  = idx - rr * 36;
                float4 v = make_float4(0.f, 0.f, 0.f, 0.f);
                if (row0 + rr < n)
                    v = reinterpret_cast<const float4*>(acc + (size_t)(row0 + rr) * FIN)[cc];
                float* dst = As + rr * AS_STRIDE + cc * 4;
                dst[0] = v.x; dst[1] = v.y; dst[2] = v.z; dst[3] = v.w;
            }
        }
        __syncthreads();

        unsigned long long p2[4][4];
        #pragma unroll
        for (int q = 0; q < 4; q++)
            #pragma unroll
            for (int j = 0; j < 4; j++) p2[q][j] = 0ull;

        #pragma unroll 4
        for (int k = 0; k < FIN; k++) {
            const unsigned long long* Wrow =
                reinterpret_cast<const unsigned long long*>(Ws + k * 128 + c0);
            unsigned long long w0 = Wrow[0], w1 = Wrow[1], w2 = Wrow[2], w3 = Wrow[3];
            #pragma unroll
            for (int q = 0; q < 4; q++) {
                unsigned long long a2 = pack_dup(As[(r + 32 * q) * AS_STRIDE + k]);
                ffma2(p2[q][0], a2, w0);
                ffma2(p2[q][1], a2, w1);
                ffma2(p2[q][2], a2, w2);
                ffma2(p2[q][3], a2, w3);
            }
        }

        const int*   cnt = cntA[et];
        const float* b   = bA[et];
        #pragma unroll
        for (int q = 0; q < 4; q++) {
            int row = row0 + r + q * 32;
            if (row < n) {
                int c = cnt[row];
                if (c > 0) {
                    float inv = 1.0f / (float)c;
                    #pragma unroll
                    for (int j = 0; j < 4; j++) {
                        float2 pv = unpack2(p2[q][j]);
                        outv[q][2 * j]     += pv.x * inv + b[c0 + 2 * j];
                        outv[q][2 * j + 1] += pv.y * inv + b[c0 + 2 * j + 1];
                    }
                }
            }
        }
    }

    const float invn = is_op ? (1.0f / 3.0f) : 0.5f;
    #pragma unroll
    for (int q = 0; q < 4; q++) {
        int row = row0 + r + q * 32;
        if (row < n) {
            float*       orow = outp  + (size_t)row * OUT_STRIDE;
            const float* frow = feats + (size_t)row * D;
            #pragma unroll
            for (int j = 0; j < 8; j++) {
                orow[c0 + j]     = frow[c0 + j];
                orow[D + c0 + j] = fmaxf(outv[q][j] * invn, 0.f);
            }
        }
    }
}

// ---------------------------------------------------------------------------
// Launch
// ---------------------------------------------------------------------------
extern "C" void kernel_launch(void* const* d_in, const int* in_sizes, int n_in,
                              void* d_out, int out_size) {
    const float* op_feats  = (const float*)d_in[0];
    const float* dev_feats = (const float*)d_in[1];

    const float* ef_link  = (const float*)d_in[2];
    const int*   src_link = (const int*)  d_in[3];
    const int*   dst_link = (const int*)  d_in[4];
    const float* W_link   = (const float*)d_in[5];
    const float* b_link   = (const float*)d_in[6];

    const float* ef_prev  = (const float*)d_in[7];
    const int*   src_prev = (const int*)  d_in[8];
    const int*   dst_prev = (const int*)  d_in[9];
    const float* W_prev   = (const float*)d_in[10];
    const float* b_prev   = (const float*)d_in[11];

    const float* ef_succ  = (const float*)d_in[12];
    const int*   src_succ = (const int*)  d_in[13];
    const int*   dst_succ = (const int*)  d_in[14];
    const float* W_succ   = (const float*)d_in[15];
    const float* b_succ   = (const float*)d_in[16];

    const float* ef_place  = (const float*)d_in[17];
    const int*   src_place = (const int*)  d_in[18];
    const int*   dst_place = (const int*)  d_in[19];
    const float* W_place   = (const float*)d_in[20];
    const float* b_place   = (const float*)d_in[21];

    const float* ef_serve  = (const float*)d_in[22];
    const int*   src_serve = (const int*)  d_in[23];
    const int*   dst_serve = (const int*)  d_in[24];
    const float* W_serve   = (const float*)d_in[25];
    const float* b_serve   = (const float*)d_in[26];

    const int ne_link  = in_sizes[3];
    const int ne_prev  = in_sizes[8];
    const int ne_succ  = in_sizes[13];
    const int ne_place = in_sizes[18];
    const int ne_serve = in_sizes[23];
    const int ne_total = ne_link + ne_prev + ne_succ + ne_place + ne_serve;

    int* cntbase = nullptr;  cudaGetSymbolAddress((void**)&cntbase, g_cnt);
    int* offbase = nullptr;  cudaGetSymbolAddress((void**)&offbase, g_off);
    int* curbase = nullptr;  cudaGetSymbolAddress((void**)&curbase, g_cur);
    int* tilesum = nullptr;  cudaGetSymbolAddress((void**)&tilesum, g_tilesum);

    // No static guard: idempotent, deterministic, capture-safe.
    cudaFuncSetAttribute(gemm_fused_kernel,
                         cudaFuncAttributeMaxDynamicSharedMemorySize,
                         GEMM_SMEM_BYTES);

    // 0) zero counters
    zero_cnt_kernel<<<(NSEG + 255) / 256, 256>>>(cntbase, NSEG);

    // 1) histogram
    hist_kernel<<<(ne_total + 255) / 256, 256>>>(
        dst_prev, ne_prev, dst_succ, ne_succ, dst_serve, ne_serve,
        dst_link, ne_link, dst_place, ne_place);

    // 2-3) scan
    int ntiles = (NSEG + 1023) / 1024;  // 157
    scan_tiles_kernel<<<ntiles, 1024>>>(cntbase, offbase, tilesum, NSEG);
    scan_fixup_kernel<<<ntiles, 1024>>>(offbase, tilesum, curbase, NSEG);

    // 4) bin
    bin_kernel<<<(ne_total + 255) / 256, 256>>>(
        dst_prev, ne_prev, dst_succ, ne_succ, dst_serve, ne_serve,
        dst_link, ne_link, dst_place, ne_place);

    // 5) fused gather (one warp per segment)
    gather_fused_kernel<<<(NSEG + 7) / 8, 256>>>(
        op_feats, dev_feats,
        ef_prev, src_prev, ef_succ, src_succ, ef_serve, src_serve,
        ef_link, src_link, ef_place, src_place);

    // 6) fused GEMM
    gemm_fused_kernel<<<GRID_OP + GRID_DEV, 512, GEMM_SMEM_BYTES>>>(
        op_feats, dev_feats,
        W_prev, b_prev, W_succ, b_succ, W_serve, b_serve,
        W_link, b_link, W_place, b_place,
        (float*)d_out);

    (void)n_in; (void)out_size;
}

// round 8
// speedup vs baseline: 2.0077x; 1.0966x over previous
#include <cuda_runtime.h>

// Problem constants
#define N_OP   50000
#define N_DEV  5000
#define D      128
#define DE     16
#define FIN    144        // D + DE
#define OUTF   128
#define OUT_STRIDE 256    // D + OUTF

#define NE_TOTAL 2480000
#define NSEG     160000

// Segment bases (stacked order: prev, succ, serve, link, place)
#define SEG_PREV   0
#define SEG_SUCC   50000
#define SEG_SERVE  100000
#define SEG_LINK   150000
#define SEG_PLACE  155000

#define OFF_ACC_PREV   0
#define OFF_ACC_SUCC   7200000
#define OFF_ACC_SERVE  14400000
#define OFF_ACC_LINK   21600000
#define OFF_ACC_PLACE  22320000
#define ACC_FLOATS     23040000

#define GRID_OP  391      // ceil(50000/128)
#define GRID_DEV 40       // ceil(5000/128)

__device__ float g_acc[ACC_FLOATS];
__device__ int   g_cnt[NSEG];
__device__ int   g_off[NSEG];
__device__ int   g_cur[NSEG];
__device__ int   g_tilesum[256];
__device__ int   g_slots[NE_TOTAL];

// ---------------------------------------------------------------------------
// f32x2 packed math helpers (sm_100a)
// ---------------------------------------------------------------------------
__device__ __forceinline__ void ffma2(unsigned long long& acc,
                                      unsigned long long a,
                                      unsigned long long b) {
    asm("fma.rn.f32x2 %0, %1, %2, %0;" : "+l"(acc) : "l"(a), "l"(b));
}
__device__ __forceinline__ unsigned long long pack_dup(float x) {
    unsigned long long r;
    asm("mov.b64 %0, {%1, %1};" : "=l"(r) : "f"(x));
    return r;
}
__device__ __forceinline__ float2 unpack2(unsigned long long v) {
    float2 f;
    asm("mov.b64 {%0, %1}, %2;" : "=f"(f.x), "=f"(f.y) : "l"(v));
    return f;
}

// ---------------------------------------------------------------------------
// 0) zero counters
// ---------------------------------------------------------------------------
__global__ void zero_cnt_kernel(int* __restrict__ p, int n) {
    int i = blockIdx.x * blockDim.x + threadIdx.x;
    if (i < n) p[i] = 0;
}

// ---------------------------------------------------------------------------
// 1) histogram over all edges (stacked)
// ---------------------------------------------------------------------------
__global__ void hist_kernel(const int* __restrict__ d0, int n0,
                            const int* __restrict__ d1, int n1,
                            const int* __restrict__ d2, int n2,
                            const int* __restrict__ d3, int n3,
                            const int* __restrict__ d4, int n4) {
    int i = blockIdx.x * blockDim.x + threadIdx.x;
    if (i < n0) { atomicAdd(&g_cnt[SEG_PREV  + d0[i]], 1); return; } i -= n0;
    if (i < n1) { atomicAdd(&g_cnt[SEG_SUCC  + d1[i]], 1); return; } i -= n1;
    if (i < n2) { atomicAdd(&g_cnt[SEG_SERVE + d2[i]], 1); return; } i -= n2;
    if (i < n3) { atomicAdd(&g_cnt[SEG_LINK  + d3[i]], 1); return; } i -= n3;
    if (i < n4) { atomicAdd(&g_cnt[SEG_PLACE + d4[i]], 1); }
}

// ---------------------------------------------------------------------------
// 2) per-tile exclusive scan (1024/tile) + tile totals
// ---------------------------------------------------------------------------
__global__ __launch_bounds__(1024)
void scan_tiles_kernel(const int* __restrict__ cnt, int* __restrict__ off,
                       int* __restrict__ tilesum, int n) {
    __shared__ int warp_sums[32];
    int tid  = threadIdx.x;
    int gid  = blockIdx.x * 1024 + tid;
    int lane = tid & 31, wid = tid >> 5;
    int v = (gid < n) ? cnt[gid] : 0;

    int x = v;
    #pragma unroll
    for (int d = 1; d < 32; d <<= 1) {
        int y = __shfl_up_sync(0xffffffffu, x, d);
        if (lane >= d) x += y;
    }
    if (lane == 31) warp_sums[wid] = x;
    __syncthreads();
    if (wid == 0) {
        int s = warp_sums[lane];
        #pragma unroll
        for (int d = 1; d < 32; d <<= 1) {
            int y = __shfl_up_sync(0xffffffffu, s, d);
            if (lane >= d) s += y;
        }
        warp_sums[lane] = s;
    }
    __syncthreads();
    int warp_off = (wid > 0) ? warp_sums[wid - 1] : 0;
    int incl = x + warp_off;
    if (gid < n) off[gid] = incl - v;
    if (tid == 1023) tilesum[blockIdx.x] = incl;
}

// ---------------------------------------------------------------------------
// 3) fixup: add prefix of tile sums, init cursors (one block per tile)
// ---------------------------------------------------------------------------
__global__ __launch_bounds__(1024)
void scan_fixup_kernel(int* __restrict__ off, const int* __restrict__ tilesum,
                       int* __restrict__ cur, int n) {
    __shared__ int red[32];
    __shared__ int s_prefix;
    int t    = blockIdx.x;
    int tid  = threadIdx.x;
    int lane = tid & 31, wid = tid >> 5;

    int partial = 0;
    for (int i = tid; i < t; i += 1024) partial += tilesum[i];
    #pragma unroll
    for (int d = 16; d > 0; d >>= 1)
        partial += __shfl_down_sync(0xffffffffu, partial, d);
    if (lane == 0) red[wid] = partial;
    __syncthreads();
    if (tid < 32) {
        int v = red[tid];
        #pragma unroll
        for (int d = 16; d > 0; d >>= 1)
            v += __shfl_down_sync(0xffffffffu, v, d);
        if (tid == 0) s_prefix = v;
    }
    __syncthreads();
    int prefix = s_prefix;

    int gid = t * 1024 + tid;
    if (gid < n) {
        int o = off[gid] + prefix;
        off[gid] = o;
        cur[gid] = o;
    }
}

// ---------------------------------------------------------------------------
// 4) bin edge IDs into dst buckets
// ---------------------------------------------------------------------------
__global__ void bin_kernel(const int* __restrict__ d0, int n0,
                           const int* __restrict__ d1, int n1,
                           const int* __restrict__ d2, int n2,
                           const int* __restrict__ d3, int n3,
                           const int* __restrict__ d4, int n4) {
    int e = blockIdx.x * blockDim.x + threadIdx.x;
    if (e < n0) { int s = atomicAdd(&g_cur[SEG_PREV  + d0[e]], 1); g_slots[s] = e; return; } e -= n0;
    if (e < n1) { int s = atomicAdd(&g_cur[SEG_SUCC  + d1[e]], 1); g_slots[s] = e; return; } e -= n1;
    if (e < n2) { int s = atomicAdd(&g_cur[SEG_SERVE + d2[e]], 1); g_slots[s] = e; return; } e -= n2;
    if (e < n3) { int s = atomicAdd(&g_cur[SEG_LINK  + d3[e]], 1); g_slots[s] = e; return; } e -= n3;
    if (e < n4) { int s = atomicAdd(&g_cur[SEG_PLACE + d4[e]], 1); g_slots[s] = e; }
}

// ---------------------------------------------------------------------------
// 5) fused gather: one warp per (etype, dst) segment. R5 structure (lane owns
// a fixed float4 slot of the 128-float row), with the edge loop explicitly
// unrolled by 4: all four row loads issue before any accumulation -> 4
// independent LDG.128 in flight per group. ef loads use 16 lanes per quad
// (lane>>2 = edge, lane&3 = chunk), reduced at the end via xor(4), xor(8).
// ---------------------------------------------------------------------------
__global__ __launch_bounds__(256)
void gather_fused_kernel(const float* __restrict__ op_feats,
                         const float* __restrict__ dev_feats,
                         const float* __restrict__ ef_prev,  const int* __restrict__ src_prev,
                         const float* __restrict__ ef_succ,  const int* __restrict__ src_succ,
                         const float* __restrict__ ef_serve, const int* __restrict__ src_serve,
                         const float* __restrict__ ef_link,  const int* __restrict__ src_link,
                         const float* __restrict__ ef_place, const int* __restrict__ src_place) {
    int seg = blockIdx.x * 8 + (threadIdx.x >> 5);
    if (seg >= NSEG) return;
    const int lane = threadIdx.x & 31;

    const float* sf; const float* ef; const int* src; float* acc; int local;
    if (seg < SEG_SUCC)       { sf = op_feats;  ef = ef_prev;  src = src_prev;  acc = g_acc + OFF_ACC_PREV;  local = seg; }
    else if (seg < SEG_SERVE) { sf = op_feats;  ef = ef_succ;  src = src_succ;  acc = g_acc + OFF_ACC_SUCC;  local = seg - SEG_SUCC; }
    else if (seg < SEG_LINK)  { sf = dev_feats; ef = ef_serve; src = src_serve; acc = g_acc + OFF_ACC_SERVE; local = seg - SEG_SERVE; }
    else if (seg < SEG_PLACE) { sf = dev_feats; ef = ef_link;  src = src_link;  acc = g_acc + OFF_ACC_LINK;  local = seg - SEG_LINK; }
    else                      { sf = op_feats;  ef = ef_place; src = src_place; acc = g_acc + OFF_ACC_PLACE; local = seg - SEG_PLACE; }

    int m = g_cnt[seg];
    if (m == 0) return;
    int base = g_off[seg];

    float4 f  = make_float4(0.f, 0.f, 0.f, 0.f);
    float4 e4 = make_float4(0.f, 0.f, 0.f, 0.f);  // lanes 0..15: ef chunk (lane&3) partials

    for (int c = 0; c < m; c += 32) {
        int k = c + lane;
        int eidx = 0, sidx = 0;
        if (k < m) {
            eidx = __ldg(&g_slots[base + k]);
            sidx = __ldg(&src[eidx]);
        }
        int iter = min(32, m - c);

        int i = 0;
        for (; i + 4 <= iter; i += 4) {
            int s0 = __shfl_sync(0xffffffffu, sidx, i + 0);
            int s1 = __shfl_sync(0xffffffffu, sidx, i + 1);
            int s2 = __shfl_sync(0xffffffffu, sidx, i + 2);
            int s3 = __shfl_sync(0xffffffffu, sidx, i + 3);
            int emy = __shfl_sync(0xffffffffu, eidx, i + (lane >> 2)); // edge for my ef lane
            // four independent full-row loads
            float4 v0 = __ldg(reinterpret_cast<const float4*>(sf + (size_t)s0 * D) + lane);
            float4 v1 = __ldg(reinterpret_cast<const float4*>(sf + (size_t)s1 * D) + lane);
            float4 v2 = __ldg(reinterpret_cast<const float4*>(sf + (size_t)s2 * D) + lane);
            float4 v3 = __ldg(reinterpret_cast<const float4*>(sf + (size_t)s3 * D) + lane);
            // ef: lanes 0..15 cover 4 edges x 4 chunks
            if (lane < 16) {
                float4 t = __ldg(reinterpret_cast<const float4*>(ef + (size_t)emy * DE) + (lane & 3));
                e4.x += t.x; e4.y += t.y; e4.z += t.z; e4.w += t.w;
            }
            f.x += v0.x; f.y += v0.y; f.z += v0.z; f.w += v0.w;
            f.x += v1.x; f.y += v1.y; f.z += v1.z; f.w += v1.w;
            f.x += v2.x; f.y += v2.y; f.z += v2.z; f.w += v2.w;
            f.x += v3.x; f.y += v3.y; f.z += v3.z; f.w += v3.w;
        }
        // tail (<= 3 edges)
        for (; i < iter; i++) {
            int s = __shfl_sync(0xffffffffu, sidx, i);
            int e = __shfl_sync(0xffffffffu, eidx, i);
            float4 v = __ldg(reinterpret_cast<const float4*>(sf + (size_t)s * D) + lane);
            f.x += v.x; f.y += v.y; f.z += v.z; f.w += v.w;
            if (lane < 4) {
                float4 t = __ldg(reinterpret_cast<const float4*>(ef + (size_t)e * DE) + lane);
                e4.x += t.x; e4.y += t.y; e4.z += t.z; e4.w += t.w;
            }
        }
    }

    // reduce e4 across the 4 ef-lane groups (lanes {c, c+4, c+8, c+12})
    e4.x += __shfl_xor_sync(0xffffffffu, e4.x, 4);
    e4.y += __shfl_xor_sync(0xffffffffu, e4.y, 4);
    e4.z += __shfl_xor_sync(0xffffffffu, e4.z, 4);
    e4.w += __shfl_xor_sync(0xffffffffu, e4.w, 4);
    e4.x += __shfl_xor_sync(0xffffffffu, e4.x, 8);
    e4.y += __shfl_xor_sync(0xffffffffu, e4.y, 8);
    e4.z += __shfl_xor_sync(0xffffffffu, e4.z, 8);
    e4.w += __shfl_xor_sync(0xffffffffu, e4.w, 8);

    float* arow = acc + (size_t)local * FIN;
    reinterpret_cast<float4*>(arow)[lane] = f;
    if (lane < 4) reinterpret_cast<float4*>(arow + D)[lane] = e4;
}

// ---------------------------------------------------------------------------
// 6) fused GEMM (op + dev tiles in one grid), whole-K smem residency, f32x2.
// ---------------------------------------------------------------------------
#define AS_STRIDE 145
#define AS_FLOATS (128 * AS_STRIDE)
#define WS_FLOATS (144 * 128)
#define GEMM_SMEM_BYTES ((AS_FLOATS + WS_FLOATS) * 4)

__global__ __launch_bounds__(512)
void gemm_fused_kernel(const float* __restrict__ op_feats,
                       const float* __restrict__ dev_feats,
                       const float* __restrict__ W_prev,  const float* __restrict__ b_prev,
                       const float* __restrict__ W_succ,  const float* __restrict__ b_succ,
                       const float* __restrict__ W_serve, const float* __restrict__ b_serve,
                       const float* __restrict__ W_link,  const float* __restrict__ b_link,
                       const float* __restrict__ W_place, const float* __restrict__ b_place,
                       float* __restrict__ out) {
    extern __shared__ float sm[];
    float* As = sm;                 // [128][145]
    float* Ws = sm + AS_FLOATS;     // [144][128]

    const int tid = threadIdx.x;
    const int r   = tid & 31;
    const int c0  = (tid >> 5) * 8;

    const bool is_op = blockIdx.x < GRID_OP;
    const int  net   = is_op ? 3 : 2;
    const int  row0  = (is_op ? blockIdx.x : (blockIdx.x - GRID_OP)) * 128;
    const int  n     = is_op ? N_OP : N_DEV;

    const float* feats = is_op ? op_feats : dev_feats;
    const float* accA[3]; const int* cntA[3]; const float* WA[3]; const float* bA[3];
    if (is_op) {
        accA[0] = g_acc + OFF_ACC_PREV;  cntA[0] = g_cnt + SEG_PREV;  WA[0] = W_prev;  bA[0] = b_prev;
        accA[1] = g_acc + OFF_ACC_SUCC;  cntA[1] = g_cnt + SEG_SUCC;  WA[1] = W_succ;  bA[1] = b_succ;
        accA[2] = g_acc + OFF_ACC_SERVE; cntA[2] = g_cnt + SEG_SERVE; WA[2] = W_serve; bA[2] = b_serve;
    } else {
        accA[0] = g_acc + OFF_ACC_LINK;  cntA[0] = g_cnt + SEG_LINK;  WA[0] = W_link;  bA[0] = b_link;
        accA[1] = g_acc + OFF_ACC_PLACE; cntA[1] = g_cnt + SEG_PLACE; WA[1] = W_place; bA[1] = b_place;
        accA[2] = accA[1]; cntA[2] = cntA[1]; WA[2] = WA[1]; bA[2] = bA[1];
    }
    float* outp = is_op ? out : (out + (size_t)N_OP * OUT_STRIDE);

    float outv[4][8];
    #pragma unroll
    for (int q = 0; q < 4; q++)
        #pragma unroll
        for (int j = 0; j < 8; j++) outv[q][j] = 0.f;

    for (int et = 0; et < net; et++) {
        const float* acc = accA[et];
        const float* W   = WA[et];

        __syncthreads();
        {
            const float4* W4 = reinterpret_cast<const float4*>(W);
            float4* Ws4 = reinterpret_cast<float4*>(Ws);
            #pragma unroll
            for (int i = 0; i < 9; i++) Ws4[tid + i * 512] = W4[tid + i * 512];
        }
        {
            #pragma unroll
            for (int i = 0; i < 9; i++) {
                int idx = tid + i * 512;
                int rr  = idx / 36;
                int cc  = idx - rr * 36;
                float4 v = make_float4(0.f, 0.f, 0.f, 0.f);
                if (row0 + rr < n)
                    v = reinterpret_cast<const float4*>(acc + (size_t)(row0 + rr) * FIN)[cc];
                float* dst = As + rr * AS_STRIDE + cc * 4;
                dst[0] = v.x; dst[1] = v.y; dst[2] = v.z; dst[3] = v.w;
            }
        }
        __syncthreads();

        unsigned long long p2[4][4];
        #pragma unroll
        for (int q = 0; q < 4; q++)
            #pragma unroll
            for (int j = 0; j < 4; j++) p2[q][j] = 0ull;

        #pragma unroll 4
        for (int k = 0; k < FIN; k++) {
            const unsigned long long* Wrow =
                reinterpret_cast<const unsigned long long*>(Ws + k * 128 + c0);
            unsigned long long w0 = Wrow[0], w1 = Wrow[1], w2 = Wrow[2], w3 = Wrow[3];
            #pragma unroll
            for (int q = 0; q < 4; q++) {
                unsigned long long a2 = pack_dup(As[(r + 32 * q) * AS_STRIDE + k]);
                ffma2(p2[q][0], a2, w0);
                ffma2(p2[q][1], a2, w1);
                ffma2(p2[q][2], a2, w2);
                ffma2(p2[q][3], a2, w3);
            }
        }

        const int*   cnt = cntA[et];
        const float* b   = bA[et];
        #pragma unroll
        for (int q = 0; q < 4; q++) {
            int row = row0 + r + q * 32;
            if (row < n) {
                int c = cnt[row];
                if (c > 0) {
                    float inv = 1.0f / (float)c;
                    #pragma unroll
                    for (int j = 0; j < 4; j++) {
                        float2 pv = unpack2(p2[q][j]);
                        outv[q][2 * j]     += pv.x * inv + b[c0 + 2 * j];
                        outv[q][2 * j + 1] += pv.y * inv + b[c0 + 2 * j + 1];
                    }
                }
            }
        }
    }

    const float invn = is_op ? (1.0f / 3.0f) : 0.5f;
    #pragma unroll
    for (int q = 0; q < 4; q++) {
        int row = row0 + r + q * 32;
        if (row < n) {
            float*       orow = outp  + (size_t)row * OUT_STRIDE;
            const float* frow = feats + (size_t)row * D;
            #pragma unroll
            for (int j = 0; j < 8; j++) {
                orow[c0 + j]     = frow[c0 + j];
                orow[D + c0 + j] = fmaxf(outv[q][j] * invn, 0.f);
            }
        }
    }
}

// ---------------------------------------------------------------------------
// Launch
// ---------------------------------------------------------------------------
extern "C" void kernel_launch(void* const* d_in, const int* in_sizes, int n_in,
                              void* d_out, int out_size) {
    const float* op_feats  = (const float*)d_in[0];
    const float* dev_feats = (const float*)d_in[1];

    const float* ef_link  = (const float*)d_in[2];
    const int*   src_link = (const int*)  d_in[3];
    const int*   dst_link = (const int*)  d_in[4];
    const float* W_link   = (const float*)d_in[5];
    const float* b_link   = (const float*)d_in[6];

    const float* ef_prev  = (const float*)d_in[7];
    const int*   src_prev = (const int*)  d_in[8];
    const int*   dst_prev = (const int*)  d_in[9];
    const float* W_prev   = (const float*)d_in[10];
    const float* b_prev   = (const float*)d_in[11];

    const float* ef_succ  = (const float*)d_in[12];
    const int*   src_succ = (const int*)  d_in[13];
    const int*   dst_succ = (const int*)  d_in[14];
    const float* W_succ   = (const float*)d_in[15];
    const float* b_succ   = (const float*)d_in[16];

    const float* ef_place  = (const float*)d_in[17];
    const int*   src_place = (const int*)  d_in[18];
    const int*   dst_place = (const int*)  d_in[19];
    const float* W_place   = (const float*)d_in[20];
    const float* b_place   = (const float*)d_in[21];

    const float* ef_serve  = (const float*)d_in[22];
    const int*   src_serve = (const int*)  d_in[23];
    const int*   dst_serve = (const int*)  d_in[24];
    const float* W_serve   = (const float*)d_in[25];
    const float* b_serve   = (const float*)d_in[26];

    const int ne_link  = in_sizes[3];
    const int ne_prev  = in_sizes[8];
    const int ne_succ  = in_sizes[13];
    const int ne_place = in_sizes[18];
    const int ne_serve = in_sizes[23];
    const int ne_total = ne_link + ne_prev + ne_succ + ne_place + ne_serve;

    int* cntbase = nullptr;  cudaGetSymbolAddress((void**)&cntbase, g_cnt);
    int* offbase = nullptr;  cudaGetSymbolAddress((void**)&offbase, g_off);
    int* curbase = nullptr;  cudaGetSymbolAddress((void**)&curbase, g_cur);
    int* tilesum = nullptr;  cudaGetSymbolAddress((void**)&tilesum, g_tilesum);

    cudaFuncSetAttribute(gemm_fused_kernel,
                         cudaFuncAttributeMaxDynamicSharedMemorySize,
                         GEMM_SMEM_BYTES);

    // 0) zero counters
    zero_cnt_kernel<<<(NSEG + 255) / 256, 256>>>(cntbase, NSEG);

    // 1) histogram
    hist_kernel<<<(ne_total + 255) / 256, 256>>>(
        dst_prev, ne_prev, dst_succ, ne_succ, dst_serve, ne_serve,
        dst_link, ne_link, dst_place, ne_place);

    // 2-3) scan
    int ntiles = (NSEG + 1023) / 1024;  // 157
    scan_tiles_kernel<<<ntiles, 1024>>>(cntbase, offbase, tilesum, NSEG);
    scan_fixup_kernel<<<ntiles, 1024>>>(offbase, tilesum, curbase, NSEG);

    // 4) bin
    bin_kernel<<<(ne_total + 255) / 256, 256>>>(
        dst_prev, ne_prev, dst_succ, ne_succ, dst_serve, ne_serve,
        dst_link, ne_link, dst_place, ne_place);

    // 5) fused gather (one warp per segment, explicit 4-edge load batching)
    gather_fused_kernel<<<(NSEG + 7) / 8, 256>>>(
        op_feats, dev_feats,
        ef_prev, src_prev, ef_succ, src_succ, ef_serve, src_serve,
        ef_link, src_link, ef_place, src_place);

    // 6) fused GEMM
    gemm_fused_kernel<<<GRID_OP + GRID_DEV, 512, GEMM_SMEM_BYTES>>>(
        op_feats, dev_feats,
        W_prev, b_prev, W_succ, b_succ, W_serve, b_serve,
        W_link, b_link, W_place, b_place,
        (float*)d_out);

    (void)n_in; (void)out_size;
}